// round 3
// baseline (speedup 1.0000x reference)
#include <cuda_runtime.h>
#include <math.h>

// Problem constants (fixed shapes from reference)
#define B_    4
#define S_    4096
#define H_    16
#define D_    128
#define HALF_ 64
#define MAX_OFFSET_ 512
#define MAX_POS_ (S_ + MAX_OFFSET_)   // 4608

// Scratch tables: cos/sin[pos][freq], pos in [0, 4608), freq in [0, 64)
__device__ float g_cos_tab[MAX_POS_ * HALF_];
__device__ float g_sin_tab[MAX_POS_ * HALF_];

__global__ void build_rope_tables() {
    int idx = blockIdx.x * blockDim.x + threadIdx.x;
    if (idx >= MAX_POS_ * HALF_) return;
    int pos = idx >> 6;     // /64
    int i   = idx & 63;     // %64
    // inv_freq = 10000^(-2i/128) = exp(-ln(10000) * i/64), computed in double
    // then rounded to fp32 (within 0.5 ulp of truth; jax fp32 pow is within ~2 ulp).
    float inv = (float)exp(-log(10000.0) * ((double)i / 64.0));
    // Match reference rounding: freq = fp32(pos) * fp32(inv) rounded to fp32,
    // then accurate sin/cos of that fp32 value.
    float freq = (float)pos * inv;
    float s, c;
    sincosf(freq, &s, &c);
    g_cos_tab[idx] = c;
    g_sin_tab[idx] = s;
}

// One thread per (row, j) where row indexes (b,s,t,h) and j in [0,16) selects a
// float4 within the first half of D. Thread loads float4 at d=4j and d=4j+64,
// rotates (q,k) or copies (v), writes both. 16 threads per 128-float row ->
// fully coalesced 128B transactions.
__global__ void __launch_bounds__(256) rope_kernel(
    const float4* __restrict__ qkv,
    const int*    __restrict__ offsets,
    float4*       __restrict__ out)
{
    int pid = blockIdx.x * blockDim.x + threadIdx.x;
    // total threads = B*S*3*H*16 = 12,582,912 (exact multiple of 256)
    int j   = pid & 15;      // float4 index within half
    int row = pid >> 4;      // (b,s,t,h) row, 128 floats = 32 float4

    int base = row * 32;     // float4 units; max ~25.2M < 2^31
    float4 x1 = qkv[base + j];
    float4 x2 = qkv[base + 16 + j];

    int t = (row >> 4) % 3;  // h is the low 4 bits (H=16); t is warp-uniform

    if (t == 2) {
        // v: straight copy
        out[base + j]      = x1;
        out[base + 16 + j] = x2;
    } else {
        int bs = row / 48;       // = b*S + s
        int s  = bs & (S_ - 1);
        int b  = bs >> 12;
        int pos = offsets[b] + s;

        const float4* cp = reinterpret_cast<const float4*>(g_cos_tab + pos * HALF_);
        const float4* sp = reinterpret_cast<const float4*>(g_sin_tab + pos * HALF_);
        float4 c  = cp[j];
        float4 sn = sp[j];

        float4 o1, o2;
        o1.x = fmaf(x1.x, c.x, -x2.x * sn.x);
        o1.y = fmaf(x1.y, c.y, -x2.y * sn.y);
        o1.z = fmaf(x1.z, c.z, -x2.z * sn.z);
        o1.w = fmaf(x1.w, c.w, -x2.w * sn.w);
        o2.x = fmaf(x1.x, sn.x, x2.x * c.x);
        o2.y = fmaf(x1.y, sn.y, x2.y * c.y);
        o2.z = fmaf(x1.z, sn.z, x2.z * c.z);
        o2.w = fmaf(x1.w, sn.w, x2.w * c.w);

        out[base + j]      = o1;
        out[base + 16 + j] = o2;
    }
}

extern "C" void kernel_launch(void* const* d_in, const int* in_sizes, int n_in,
                              void* d_out, int out_size) {
    const float4* qkv     = (const float4*)d_in[0];
    const int*    offsets = (const int*)d_in[1];
    float4*       out     = (float4*)d_out;

    // 1) Build cos/sin tables (deterministic, rebuilt every launch)
    {
        int n = MAX_POS_ * HALF_;
        build_rope_tables<<<(n + 255) / 256, 256>>>();
    }
    // 2) Main streaming kernel
    {
        int total = B_ * S_ * 3 * H_ * (HALF_ / 4);  // 12,582,912
        rope_kernel<<<total / 256, 256>>>(qkv, offsets, out);
    }
}

// round 4
// speedup vs baseline: 1.1913x; 1.1913x over previous
#include <cuda_runtime.h>
#include <math.h>

// Problem constants (fixed shapes from reference)
#define B_    4
#define S_    4096
#define H_    16
#define D_    128
#define HALF_ 64
#define MAX_OFFSET_ 512
#define MAX_POS_ (S_ + MAX_OFFSET_)   // 4608

// Scratch: 64 inverse frequencies + cos/sin tables [pos][freq]
__device__ float g_inv_freq[HALF_];
__device__ float g_cos_tab[MAX_POS_ * HALF_];
__device__ float g_sin_tab[MAX_POS_ * HALF_];

// Stage 0: 64 threads compute inv_freq in double precision ONCE.
// (Previously every table thread did two double transcendentals -> ~30us.)
__global__ void build_inv_freq() {
    int i = threadIdx.x;
    if (i < HALF_) {
        g_inv_freq[i] = (float)exp(-log(10000.0) * ((double)i / 64.0));
    }
}

// Stage 1: cos/sin tables. Pure fp32: one mul + sincosf (fast path) per entry.
__global__ void __launch_bounds__(256) build_rope_tables() {
    int idx = blockIdx.x * blockDim.x + threadIdx.x;
    if (idx >= MAX_POS_ * HALF_) return;
    int pos = idx >> 6;     // /64
    int i   = idx & 63;     // %64
    float freq = (float)pos * g_inv_freq[i];
    float s, c;
    sincosf(freq, &s, &c);
    g_cos_tab[idx] = c;
    g_sin_tab[idx] = s;
}

// One thread per (row, j): row = (b,s,t,h), j in [0,16) picks a float4 in the
// first half of D. Loads float4 at d=4j and d=4j+64, rotates (q,k) or copies
// (v), writes both. 16 threads/row -> fully coalesced 128B transactions.
// qkv/out are zero-reuse streams -> evict-first (.cs). Tables are reused 32x
// per position -> default caching.
__global__ void __launch_bounds__(256) rope_kernel(
    const float4* __restrict__ qkv,
    const int*    __restrict__ offsets,
    float4*       __restrict__ out)
{
    int pid = blockIdx.x * blockDim.x + threadIdx.x;
    int j   = pid & 15;      // float4 index within half
    int row = pid >> 4;      // (b,s,t,h) row = 32 float4

    long base = (long)row * 32;
    float4 x1 = __ldcs(&qkv[base + j]);
    float4 x2 = __ldcs(&qkv[base + 16 + j]);

    int t = (row >> 4) % 3;  // h = low 4 bits (H=16); t is warp-uniform

    if (t == 2) {
        __stcs(&out[base + j],      x1);
        __stcs(&out[base + 16 + j], x2);
    } else {
        int bs = row / 48;       // = b*S + s
        int s  = bs & (S_ - 1);
        int b  = bs >> 12;
        int pos = offsets[b] + s;

        const float4* cp = reinterpret_cast<const float4*>(g_cos_tab + pos * HALF_);
        const float4* sp = reinterpret_cast<const float4*>(g_sin_tab + pos * HALF_);
        float4 c  = cp[j];
        float4 sn = sp[j];

        float4 o1, o2;
        o1.x = fmaf(x1.x, c.x, -x2.x * sn.x);
        o1.y = fmaf(x1.y, c.y, -x2.y * sn.y);
        o1.z = fmaf(x1.z, c.z, -x2.z * sn.z);
        o1.w = fmaf(x1.w, c.w, -x2.w * sn.w);
        o2.x = fmaf(x1.x, sn.x, x2.x * c.x);
        o2.y = fmaf(x1.y, sn.y, x2.y * c.y);
        o2.z = fmaf(x1.z, sn.z, x2.z * c.z);
        o2.w = fmaf(x1.w, sn.w, x2.w * c.w);

        __stcs(&out[base + j],      o1);
        __stcs(&out[base + 16 + j], o2);
    }
}

extern "C" void kernel_launch(void* const* d_in, const int* in_sizes, int n_in,
                              void* d_out, int out_size) {
    const float4* qkv     = (const float4*)d_in[0];
    const int*    offsets = (const int*)d_in[1];
    float4*       out     = (float4*)d_out;

    build_inv_freq<<<1, 64>>>();
    {
        int n = MAX_POS_ * HALF_;
        build_rope_tables<<<(n + 255) / 256, 256>>>();
    }
    {
        int total = B_ * S_ * 3 * H_ * (HALF_ / 4);  // 12,582,912
        rope_kernel<<<total / 256, 256>>>(qkv, offsets, out);
    }
}

// round 5
// speedup vs baseline: 1.1916x; 1.0003x over previous
#include <cuda_runtime.h>
#include <math.h>

// Problem constants (fixed shapes from reference)
#define B_    4
#define S_    4096
#define H_    16
#define D_    128
#define HALF_ 64
#define MAX_OFFSET_ 512
#define MAX_POS_ (S_ + MAX_OFFSET_)   // 4608

// Scratch: cos/sin tables [pos][freq]
__device__ float g_cos_tab[MAX_POS_ * HALF_];
__device__ float g_sin_tab[MAX_POS_ * HALF_];

// inv_freq passed by value as a kernel parameter (lands in constant space).
// Computed on the HOST in double precision -> no FP64 GPU kernel needed.
struct InvFreq { float v[HALF_]; };

// Stage 0: cos/sin tables. Pure fp32: one mul + sincosf per entry.
__global__ void __launch_bounds__(256) build_rope_tables(InvFreq inv) {
    int idx = blockIdx.x * blockDim.x + threadIdx.x;
    if (idx >= MAX_POS_ * HALF_) return;
    int pos = idx >> 6;     // /64
    int i   = idx & 63;     // %64
    float freq = (float)pos * inv.v[i];
    float s, c;
    sincosf(freq, &s, &c);
    g_cos_tab[idx] = c;
    g_sin_tab[idx] = s;
}

// One thread per (row, j): row = (b,s,t,h), j in [0,16) picks a float4 in the
// first half of D. Loads float4 at d=4j and d=4j+64, rotates (q,k) or copies
// (v), writes both. 16 threads/row -> fully coalesced 128B transactions.
// qkv/out are zero-reuse streams -> evict-first (.cs). Tables are reused 32x
// per position -> default caching.
__global__ void __launch_bounds__(256) rope_kernel(
    const float4* __restrict__ qkv,
    const int*    __restrict__ offsets,
    float4*       __restrict__ out)
{
    int pid = blockIdx.x * blockDim.x + threadIdx.x;
    int j   = pid & 15;      // float4 index within half
    int row = pid >> 4;      // (b,s,t,h) row = 32 float4

    long base = (long)row * 32;
    float4 x1 = __ldcs(&qkv[base + j]);
    float4 x2 = __ldcs(&qkv[base + 16 + j]);

    int t = (row >> 4) % 3;  // h = low 4 bits (H=16); t is warp-uniform

    if (t == 2) {
        __stcs(&out[base + j],      x1);
        __stcs(&out[base + 16 + j], x2);
    } else {
        int bs = row / 48;       // = b*S + s
        int s  = bs & (S_ - 1);
        int b  = bs >> 12;
        int pos = offsets[b] + s;

        const float4* cp = reinterpret_cast<const float4*>(g_cos_tab + pos * HALF_);
        const float4* sp = reinterpret_cast<const float4*>(g_sin_tab + pos * HALF_);
        float4 c  = cp[j];
        float4 sn = sp[j];

        float4 o1, o2;
        o1.x = fmaf(x1.x, c.x, -x2.x * sn.x);
        o1.y = fmaf(x1.y, c.y, -x2.y * sn.y);
        o1.z = fmaf(x1.z, c.z, -x2.z * sn.z);
        o1.w = fmaf(x1.w, c.w, -x2.w * sn.w);
        o2.x = fmaf(x1.x, sn.x, x2.x * c.x);
        o2.y = fmaf(x1.y, sn.y, x2.y * c.y);
        o2.z = fmaf(x1.z, sn.z, x2.z * c.z);
        o2.w = fmaf(x1.w, sn.w, x2.w * c.w);

        __stcs(&out[base + j],      o1);
        __stcs(&out[base + 16 + j], o2);
    }
}

extern "C" void kernel_launch(void* const* d_in, const int* in_sizes, int n_in,
                              void* d_out, int out_size) {
    const float4* qkv     = (const float4*)d_in[0];
    const int*    offsets = (const int*)d_in[1];
    float4*       out     = (float4*)d_out;

    // Host-side inv_freq: double precision, rounded to fp32 (same numerics as
    // the old device FP64 kernel). Deterministic; 64 floats passed by value.
    InvFreq inv;
    for (int i = 0; i < HALF_; i++) {
        inv.v[i] = (float)exp(-log(10000.0) * ((double)i / 64.0));
    }

    {
        int n = MAX_POS_ * HALF_;
        build_rope_tables<<<(n + 255) / 256, 256>>>(inv);
    }
    {
        int total = B_ * S_ * 3 * H_ * (HALF_ / 4);  // 12,582,912
        rope_kernel<<<total / 256, 256>>>(qkv, offsets, out);
    }
}

// round 7
// speedup vs baseline: 1.2188x; 1.0229x over previous
#include <cuda_runtime.h>
#include <math.h>

// Problem constants (fixed shapes from reference)
#define B_    4
#define S_    4096
#define H_    16
#define D_    128
#define HALF_ 64
#define MAX_OFFSET_ 512

// inv_freq passed by value (constant space), computed on host in double.
struct InvFreq { float v[HALF_]; };

// One block per (b, s) position. 256 threads.
//  - threads 0..63 compute the 64 cos/sin pairs for this position into smem
//    (identical numerics to the reference path: fp32 inv_freq, fp32 mul,
//    accurate sincosf).
//  - then each thread owns float4-pair j = tid&15 of three rows:
//    r = tid>>4 (q), r+16 (k), r+32 (v). 6 front-batched LDG.128, fully
//    coalesced 128B transactions, branch-free type dispatch.
// qkv/out are zero-reuse streams -> evict-first (.cs).
__global__ void __launch_bounds__(256) rope_fused_kernel(
    const float4* __restrict__ qkv,
    const int*    __restrict__ offsets,
    float4*       __restrict__ out,
    InvFreq       inv)
{
    __shared__ __align__(16) float scos[HALF_];
    __shared__ __align__(16) float ssin[HALF_];

    int bs  = blockIdx.x;          // b*S + s
    int tid = threadIdx.x;

    if (tid < HALF_) {
        int b   = bs >> 12;        // S = 4096
        int s   = bs & (S_ - 1);
        int pos = offsets[b] + s;
        float freq = (float)pos * inv.v[tid];
        float sn, c;
        sincosf(freq, &sn, &c);
        scos[tid] = c;
        ssin[tid] = sn;
    }
    __syncthreads();

    int j = tid & 15;              // float4 index within the half
    int r = tid >> 4;              // head row within q-group [0,16)

    // float4 offsets: position block = 48 rows * 32 float4 = 1536
    long base  = (long)bs * 1536;
    long qoff  = base + (long)r * 32 + j;        // q row
    long koff  = qoff + 16 * 32;                 // k row (r+16)
    long voff  = qoff + 32 * 32;                 // v row (r+32)

    // Front-batch all 6 loads (MLP=6)
    float4 q1 = __ldcs(&qkv[qoff]);
    float4 q2 = __ldcs(&qkv[qoff + 16]);
    float4 k1 = __ldcs(&qkv[koff]);
    float4 k2 = __ldcs(&qkv[koff + 16]);
    float4 v1 = __ldcs(&qkv[voff]);
    float4 v2 = __ldcs(&qkv[voff + 16]);

    float4 c  = reinterpret_cast<const float4*>(scos)[j];
    float4 sn = reinterpret_cast<const float4*>(ssin)[j];

    float4 o1, o2;
    // q rotate
    o1.x = fmaf(q1.x, c.x, -q2.x * sn.x);
    o1.y = fmaf(q1.y, c.y, -q2.y * sn.y);
    o1.z = fmaf(q1.z, c.z, -q2.z * sn.z);
    o1.w = fmaf(q1.w, c.w, -q2.w * sn.w);
    o2.x = fmaf(q1.x, sn.x, q2.x * c.x);
    o2.y = fmaf(q1.y, sn.y, q2.y * c.y);
    o2.z = fmaf(q1.z, sn.z, q2.z * c.z);
    o2.w = fmaf(q1.w, sn.w, q2.w * c.w);
    __stcs(&out[qoff],      o1);
    __stcs(&out[qoff + 16], o2);

    // k rotate
    o1.x = fmaf(k1.x, c.x, -k2.x * sn.x);
    o1.y = fmaf(k1.y, c.y, -k2.y * sn.y);
    o1.z = fmaf(k1.z, c.z, -k2.z * sn.z);
    o1.w = fmaf(k1.w, c.w, -k2.w * sn.w);
    o2.x = fmaf(k1.x, sn.x, k2.x * c.x);
    o2.y = fmaf(k1.y, sn.y, k2.y * c.y);
    o2.z = fmaf(k1.z, sn.z, k2.z * c.z);
    o2.w = fmaf(k1.w, sn.w, k2.w * c.w);
    __stcs(&out[koff],      o1);
    __stcs(&out[koff + 16], o2);

    // v copy
    __stcs(&out[voff],      v1);
    __stcs(&out[voff + 16], v2);
}

extern "C" void kernel_launch(void* const* d_in, const int* in_sizes, int n_in,
                              void* d_out, int out_size) {
    const float4* qkv     = (const float4*)d_in[0];
    const int*    offsets = (const int*)d_in[1];
    float4*       out     = (float4*)d_out;

    // Host-side inv_freq: double precision, rounded to fp32 (same numerics
    // as before). Deterministic; 64 floats passed by value.
    InvFreq inv;
    for (int i = 0; i < HALF_; i++) {
        inv.v[i] = (float)exp(-log(10000.0) * ((double)i / 64.0));
    }

    rope_fused_kernel<<<B_ * S_, 256>>>(qkv, offsets, out, inv);
}